// round 15
// baseline (speedup 1.0000x reference)
#include <cuda_runtime.h>
#include <cuda_fp16.h>
#include <cuda_bf16.h>
#include <mma.h>
#include <cstdint>

// Problem constants (fixed by the reference)
#define N_NODES 100000
#define N_PAD   100096      // multiple of 128 (wmma GEMM block tile)
#define N_EDGES 1600000
#define D       64
#define CAP     64          // ELL row capacity; Poisson(16) => P(deg>64) ~ 1e-20

#define GEMM_BLOCKS (N_PAD / 128)                  // 782
#define FILL_BLOCKS ((N_EDGES / 8 + 255) / 256)    // 782

using namespace nvcuda;

// ---------------------------------------------------------------------------
// Scratch (allocation-free rule: __device__ globals). Zero-initialized at
// module load. g_deg is left zeroed by the gather kernel after each launch.
// Rows >= N_NODES of g_yh are written as zeros by the GEMM (zero-padded x),
// so the gather's dummy row N_NODES is always 0.
// ---------------------------------------------------------------------------
__device__ int    g_deg[N_NODES];
__device__ int    g_adj[(size_t)N_NODES * CAP];    // 25.6 MB, ELL layout
__device__ __half g_yh[(size_t)N_PAD * D];         // 12.8 MB, y = x @ W (fp16)

// ---------------------------------------------------------------------------
// Kernel 1: wmma GEMM y = x @ W (fp16 in, fp32 accumulate, fp16 out).
// 128 rows per block, 16 per warp. Standalone (de-fused for true footprint).
// ---------------------------------------------------------------------------
__global__ void gemm_kernel(const float* __restrict__ x,
                            const float* __restrict__ W) {
    __shared__ alignas(16) __half sW[D * D];        //  8 KB
    __shared__ alignas(16) __half sX[128 * D];      // 16 KB
    __shared__ alignas(16) float  stage[8 * 256];   //  8 KB (per-warp 16x16)

    int t     = threadIdx.x;   // 0..255
    int rows0 = blockIdx.x * 128;
    int w     = t >> 5;        // warp 0..7
    int lane  = t & 31;

    // Convert W -> fp16 smem (1024 float4, 4 per thread)
    {
        const float4* W4 = reinterpret_cast<const float4*>(W);
        uint2* dst = reinterpret_cast<uint2*>(sW);
#pragma unroll
        for (int i = 0; i < 4; i++) {
            int f = t + i * 256;
            float4 v = W4[f];
            __half2 h0 = __floats2half2_rn(v.x, v.y);
            __half2 h1 = __floats2half2_rn(v.z, v.w);
            dst[f] = make_uint2(*reinterpret_cast<unsigned int*>(&h0),
                                *reinterpret_cast<unsigned int*>(&h1));
        }
    }
    // Convert x tile -> fp16 smem (2048 float4, 8 per thread); pad rows = 0
    {
        const float4* X4 = reinterpret_cast<const float4*>(x);
        uint2* dst = reinterpret_cast<uint2*>(sX);
#pragma unroll
        for (int i = 0; i < 8; i++) {
            int f = t + i * 256;              // float4 index within tile
            int gn = rows0 + (f >> 4);        // global row
            float4 v = make_float4(0.f, 0.f, 0.f, 0.f);
            if (gn < N_NODES)
                v = X4[(size_t)gn * (D / 4) + (f & 15)];
            __half2 h0 = __floats2half2_rn(v.x, v.y);
            __half2 h1 = __floats2half2_rn(v.z, v.w);
            dst[f] = make_uint2(*reinterpret_cast<unsigned int*>(&h0),
                                *reinterpret_cast<unsigned int*>(&h1));
        }
    }
    __syncthreads();

    // A fragments for this warp's 16 rows (k = 0..3)
    wmma::fragment<wmma::matrix_a, 16, 16, 16, __half, wmma::row_major> af[4];
#pragma unroll
    for (int k = 0; k < 4; k++)
        wmma::load_matrix_sync(af[k], sX + (w * 16) * D + k * 16, D);

    float* st = stage + w * 256;

#pragma unroll
    for (int n = 0; n < 4; n++) {
        wmma::fragment<wmma::accumulator, 16, 16, 16, float> cf;
        wmma::fill_fragment(cf, 0.0f);
#pragma unroll
        for (int k = 0; k < 4; k++) {
            wmma::fragment<wmma::matrix_b, 16, 16, 16, __half, wmma::row_major> bf;
            wmma::load_matrix_sync(bf, sW + (k * 16) * D + n * 16, D);
            wmma::mma_sync(cf, af[k], bf, cf);
        }
        wmma::store_matrix_sync(st, cf, 16, wmma::mem_row_major);
        __syncwarp();

        // convert + store this 16x16 tile: lane -> (row = lane>>1, 8 cols)
        int r  = lane >> 1;
        int c0 = (lane & 1) * 8;
        int grow = rows0 + w * 16 + r;
        const float* sp = st + r * 16 + c0;
        __half2 h0 = __floats2half2_rn(sp[0], sp[1]);
        __half2 h1 = __floats2half2_rn(sp[2], sp[3]);
        __half2 h2 = __floats2half2_rn(sp[4], sp[5]);
        __half2 h3 = __floats2half2_rn(sp[6], sp[7]);
        uint4 pk = make_uint4(*reinterpret_cast<unsigned int*>(&h0),
                              *reinterpret_cast<unsigned int*>(&h1),
                              *reinterpret_cast<unsigned int*>(&h2),
                              *reinterpret_cast<unsigned int*>(&h3));
        reinterpret_cast<uint4*>(g_yh)[((size_t)grow * D + n * 16 + c0) / 8] = pk;
        __syncwarp();
    }
}

// ---------------------------------------------------------------------------
// Kernel 2: ELL fill — 8 edges per thread (2x int4 per side, MLP=8 atomics)
// Standalone: 16 regs, 0 smem -> full occupancy for latency hiding.
// ---------------------------------------------------------------------------
__global__ void fill_kernel(const int* __restrict__ ei) {
    int i = blockIdx.x * blockDim.x + threadIdx.x;
    int e = i * 8;
    if (e >= N_EDGES) return;   // N_EDGES % 8 == 0

    int4 sa = *reinterpret_cast<const int4*>(&ei[e]);
    int4 sb = *reinterpret_cast<const int4*>(&ei[e + 4]);
    int4 ta = *reinterpret_cast<const int4*>(&ei[N_EDGES + e]);
    int4 tb = *reinterpret_cast<const int4*>(&ei[N_EDGES + e + 4]);

    int s[8]  = { sa.x, sa.y, sa.z, sa.w, sb.x, sb.y, sb.z, sb.w };
    int tt[8] = { ta.x, ta.y, ta.z, ta.w, tb.x, tb.y, tb.z, tb.w };

    int p[8];
#pragma unroll
    for (int u = 0; u < 8; u++) p[u] = atomicAdd(&g_deg[s[u]], 1);
#pragma unroll
    for (int u = 0; u < 8; u++)
        if (p[u] < CAP) g_adj[(long)s[u] * CAP + p[u]] = tt[u];
}

// ---------------------------------------------------------------------------
// Kernel 3: gather over y + normalize + bias -> out (final)
// EXACT R9 structure (measured 36-37.5 us five times). One warp per node.
// Lane = (slot, colgrp): slot=lane>>3, cg=lane&7.
// Degree-adaptive: neighbors 0..15 unconditional, 16..31 warp-uniform branch,
// 32..63 rare tail. Resets g_deg[node]=0 for the next launch.
// ---------------------------------------------------------------------------
__device__ __forceinline__ void acc_chunk(float acc[8], uint4 v) {
    float2 f0 = __half22float2(*reinterpret_cast<__half2*>(&v.x));
    float2 f1 = __half22float2(*reinterpret_cast<__half2*>(&v.y));
    float2 f2 = __half22float2(*reinterpret_cast<__half2*>(&v.z));
    float2 f3 = __half22float2(*reinterpret_cast<__half2*>(&v.w));
    acc[0] += f0.x; acc[1] += f0.y;
    acc[2] += f1.x; acc[3] += f1.y;
    acc[4] += f2.x; acc[5] += f2.y;
    acc[6] += f3.x; acc[7] += f3.y;
}

__global__ void gather_kernel(const float* __restrict__ b,
                              float*       __restrict__ out) {
    int node = (blockIdx.x * blockDim.x + threadIdx.x) >> 5;
    int lane = threadIdx.x & 31;
    if (node >= N_NODES) return;

    int slot = lane >> 3;
    int cg   = lane & 7;

    const int* arow = &g_adj[(long)node * CAP];
    // independent loads: deg, adj row (unpredicated — always in bounds)
    int deg_raw = g_deg[node];
    int a0 = arow[lane];

    // reset for the next launch (replaces the zeroing kernel)
    if (lane == 0) g_deg[node] = 0;

    int deg = deg_raw > CAP ? CAP : deg_raw;
    int d0  = deg < 32 ? deg : 32;

    const uint4* y4 = reinterpret_cast<const uint4*>(g_yh);

    float acc[8];
#pragma unroll
    for (int i = 0; i < 8; i++) acc[i] = 0.f;

    // ---- neighbors 0..15: unconditional, 4 independent loads per lane ----
    {
        int tn[4];
        uint4 v[4];
#pragma unroll
        for (int u = 0; u < 4; u++) {
            int j = u * 4 + slot;                    // 0..15
            int id = __shfl_sync(0xFFFFFFFFu, a0, j);
            tn[u] = (j < d0) ? id : N_NODES;         // dummy zero row
        }
#pragma unroll
        for (int u = 0; u < 4; u++) v[u] = y4[(size_t)tn[u] * 8 + cg];
#pragma unroll
        for (int u = 0; u < 4; u++) acc_chunk(acc, v[u]);
    }
    // ---- neighbors 16..31: warp-uniform branch (P ~ 0.43) ----
    if (d0 > 16) {
        int tn[4];
        uint4 v[4];
#pragma unroll
        for (int u = 0; u < 4; u++) {
            int j = 16 + u * 4 + slot;               // 16..31
            int id = __shfl_sync(0xFFFFFFFFu, a0, j);
            tn[u] = (j < d0) ? id : N_NODES;
        }
#pragma unroll
        for (int u = 0; u < 4; u++) v[u] = y4[(size_t)tn[u] * 8 + cg];
#pragma unroll
        for (int u = 0; u < 4; u++) acc_chunk(acc, v[u]);
    }
    // ---- neighbors 32..63: rare tail (P(deg>32) ~ 1e-4) ----
    if (deg > 32) {
        int a1 = arow[32 + lane];
        int tn[8];
        uint4 v[8];
#pragma unroll
        for (int u = 0; u < 8; u++) {
            int j = 32 + u * 4 + slot;               // 32..63
            int id = __shfl_sync(0xFFFFFFFFu, a1, j - 32);
            tn[u] = (j < deg) ? id : N_NODES;
        }
#pragma unroll
        for (int u = 0; u < 8; u++) v[u] = y4[(size_t)tn[u] * 8 + cg];
#pragma unroll
        for (int u = 0; u < 8; u++) acc_chunk(acc, v[u]);
    }

    // reduce across the 4 slots
#pragma unroll
    for (int i = 0; i < 8; i++) acc[i] += __shfl_xor_sync(0xFFFFFFFFu, acc[i], 8);
#pragma unroll
    for (int i = 0; i < 8; i++) acc[i] += __shfl_xor_sync(0xFFFFFFFFu, acc[i], 16);

    if (slot == 0) {
        float scale = 1.0f / ((float)deg_raw + 1e-6f);
        float4 b0 = reinterpret_cast<const float4*>(b)[cg * 2];
        float4 b1 = reinterpret_cast<const float4*>(b)[cg * 2 + 1];
        float4 o0 = make_float4(acc[0] * scale + b0.x, acc[1] * scale + b0.y,
                                acc[2] * scale + b0.z, acc[3] * scale + b0.w);
        float4 o1 = make_float4(acc[4] * scale + b1.x, acc[5] * scale + b1.y,
                                acc[6] * scale + b1.z, acc[7] * scale + b1.w);
        float4* dst = reinterpret_cast<float4*>(&out[(size_t)node * D + cg * 8]);
        dst[0] = o0;
        dst[1] = o1;
    }
}

// ---------------------------------------------------------------------------
// Launch
// ---------------------------------------------------------------------------
extern "C" void kernel_launch(void* const* d_in, const int* in_sizes, int n_in,
                              void* d_out, int out_size) {
    const float* x  = (const float*)d_in[0];   // [N, 64]
    const int*   ei = (const int*)  d_in[1];   // [2, E]
    const float* W  = (const float*)d_in[2];   // [64, 64]
    const float* b  = (const float*)d_in[3];   // [64]
    float* out = (float*)d_out;                // [N, 64]

    (void)in_sizes; (void)n_in; (void)out_size;

    gemm_kernel<<<GEMM_BLOCKS, 256>>>(x, W);
    fill_kernel<<<FILL_BLOCKS, 256>>>(ei);

    // one warp per node, 8 warps per block
    gather_kernel<<<(N_NODES + 7) / 8, 256>>>(b, out);
}

// round 16
// speedup vs baseline: 1.1795x; 1.1795x over previous
#include <cuda_runtime.h>
#include <cuda_fp16.h>
#include <cuda_bf16.h>
#include <mma.h>
#include <cstdint>

// Problem constants (fixed by the reference)
#define N_NODES 100000
#define N_PAD   100096      // multiple of 128 (wmma GEMM block tile)
#define N_EDGES 1600000
#define D       64
#define CAP     64          // ELL row capacity; Poisson(16) => P(deg>64) ~ 1e-20

#define GEMM_BLOCKS (N_PAD / 128)                  // 782
#define FILL_BLOCKS ((N_EDGES / 8 + 255) / 256)    // 782

// padded shared strides (conflict-free LDSM: 144B row stride rotates banks)
#define SXS 72     // halves per row for sX/sW (64 data + 8 pad)
#define STS 20     // floats per row for the stage tile (16 data + 4 pad)

using namespace nvcuda;

// ---------------------------------------------------------------------------
// Scratch (allocation-free rule: __device__ globals). Zero-initialized at
// module load. g_deg is left zeroed by the gather kernel after each launch.
// Rows >= N_NODES of g_yh are written as zeros by the GEMM (zero-padded x),
// so the gather's dummy row N_NODES is always 0.
// ---------------------------------------------------------------------------
__device__ int    g_deg[N_NODES];
__device__ int    g_adj[(size_t)N_NODES * CAP];    // 25.6 MB, ELL layout
__device__ __half g_yh[(size_t)N_PAD * D];         // 12.8 MB, y = x @ W (fp16)

// ---------------------------------------------------------------------------
// Kernel 1: wmma GEMM y = x @ W (fp16 in, fp32 accumulate, fp16 out).
// 128 rows per block, 16 per warp. Padded smem strides -> conflict-free LDSM.
// ---------------------------------------------------------------------------
__global__ void gemm_kernel(const float* __restrict__ x,
                            const float* __restrict__ W) {
    __shared__ alignas(16) __half sW[D * SXS];          //  9.2 KB
    __shared__ alignas(16) __half sX[128 * SXS];        // 18.4 KB
    __shared__ alignas(16) float  stage[8 * 16 * STS];  // 10.2 KB (per-warp 16x20)

    int t     = threadIdx.x;   // 0..255
    int rows0 = blockIdx.x * 128;
    int w     = t >> 5;        // warp 0..7
    int lane  = t & 31;

    // Convert W -> fp16 smem (1024 float4, 4 per thread), padded rows
    {
        const float4* W4 = reinterpret_cast<const float4*>(W);
#pragma unroll
        for (int i = 0; i < 4; i++) {
            int f  = t + i * 256;          // float4 index (packed)
            int k  = f >> 4;               // row 0..63
            int jg = f & 15;               // float4-group within row
            float4 v = W4[f];
            __half2 h0 = __floats2half2_rn(v.x, v.y);
            __half2 h1 = __floats2half2_rn(v.z, v.w);
            *reinterpret_cast<uint2*>(&sW[k * SXS + jg * 4]) =
                make_uint2(*reinterpret_cast<unsigned int*>(&h0),
                           *reinterpret_cast<unsigned int*>(&h1));
        }
    }
    // Convert x tile -> fp16 smem (2048 float4, 8 per thread); pad rows = 0
    {
        const float4* X4 = reinterpret_cast<const float4*>(x);
#pragma unroll
        for (int i = 0; i < 8; i++) {
            int f   = t + i * 256;         // float4 index within packed tile
            int row = f >> 4;              // tile row 0..127
            int jg  = f & 15;
            int gn  = rows0 + row;
            float4 v = make_float4(0.f, 0.f, 0.f, 0.f);
            if (gn < N_NODES)
                v = X4[(size_t)gn * (D / 4) + jg];
            __half2 h0 = __floats2half2_rn(v.x, v.y);
            __half2 h1 = __floats2half2_rn(v.z, v.w);
            *reinterpret_cast<uint2*>(&sX[row * SXS + jg * 4]) =
                make_uint2(*reinterpret_cast<unsigned int*>(&h0),
                           *reinterpret_cast<unsigned int*>(&h1));
        }
    }
    __syncthreads();

    // A fragments for this warp's 16 rows (k = 0..3)
    wmma::fragment<wmma::matrix_a, 16, 16, 16, __half, wmma::row_major> af[4];
#pragma unroll
    for (int k = 0; k < 4; k++)
        wmma::load_matrix_sync(af[k], sX + (w * 16) * SXS + k * 16, SXS);

    float* st = stage + w * 16 * STS;

#pragma unroll
    for (int n = 0; n < 4; n++) {
        wmma::fragment<wmma::accumulator, 16, 16, 16, float> cf;
        wmma::fill_fragment(cf, 0.0f);
#pragma unroll
        for (int k = 0; k < 4; k++) {
            wmma::fragment<wmma::matrix_b, 16, 16, 16, __half, wmma::row_major> bf;
            wmma::load_matrix_sync(bf, sW + (k * 16) * SXS + n * 16, SXS);
            wmma::mma_sync(cf, af[k], bf, cf);
        }
        wmma::store_matrix_sync(st, cf, STS, wmma::mem_row_major);
        __syncwarp();

        // convert + store this 16x16 tile: lane -> (row = lane>>1, 8 cols)
        int r  = lane >> 1;
        int c0 = (lane & 1) * 8;
        int grow = rows0 + w * 16 + r;
        const float* sp = st + r * STS + c0;
        __half2 h0 = __floats2half2_rn(sp[0], sp[1]);
        __half2 h1 = __floats2half2_rn(sp[2], sp[3]);
        __half2 h2 = __floats2half2_rn(sp[4], sp[5]);
        __half2 h3 = __floats2half2_rn(sp[6], sp[7]);
        uint4 pk = make_uint4(*reinterpret_cast<unsigned int*>(&h0),
                              *reinterpret_cast<unsigned int*>(&h1),
                              *reinterpret_cast<unsigned int*>(&h2),
                              *reinterpret_cast<unsigned int*>(&h3));
        reinterpret_cast<uint4*>(g_yh)[((size_t)grow * D + n * 16 + c0) / 8] = pk;
        __syncwarp();
    }
}

// ---------------------------------------------------------------------------
// Kernel 2: ELL fill — 8 edges per thread (2x int4 per side, MLP=8 atomics)
// Standalone: 16 regs, 0 smem -> full occupancy for latency hiding.
// ---------------------------------------------------------------------------
__global__ void fill_kernel(const int* __restrict__ ei) {
    int i = blockIdx.x * blockDim.x + threadIdx.x;
    int e = i * 8;
    if (e >= N_EDGES) return;   // N_EDGES % 8 == 0

    int4 sa = *reinterpret_cast<const int4*>(&ei[e]);
    int4 sb = *reinterpret_cast<const int4*>(&ei[e + 4]);
    int4 ta = *reinterpret_cast<const int4*>(&ei[N_EDGES + e]);
    int4 tb = *reinterpret_cast<const int4*>(&ei[N_EDGES + e + 4]);

    int s[8]  = { sa.x, sa.y, sa.z, sa.w, sb.x, sb.y, sb.z, sb.w };
    int tt[8] = { ta.x, ta.y, ta.z, ta.w, tb.x, tb.y, tb.z, tb.w };

    int p[8];
#pragma unroll
    for (int u = 0; u < 8; u++) p[u] = atomicAdd(&g_deg[s[u]], 1);
#pragma unroll
    for (int u = 0; u < 8; u++)
        if (p[u] < CAP) g_adj[(long)s[u] * CAP + p[u]] = tt[u];
}

// ---------------------------------------------------------------------------
// Kernel 3: gather over y + normalize + bias -> out (final)
// EXACT R9 structure (measured 36-37.5 us five times). One warp per node.
// Lane = (slot, colgrp): slot=lane>>3, cg=lane&7.
// Degree-adaptive: neighbors 0..15 unconditional, 16..31 warp-uniform branch,
// 32..63 rare tail. Resets g_deg[node]=0 for the next launch.
// ---------------------------------------------------------------------------
__device__ __forceinline__ void acc_chunk(float acc[8], uint4 v) {
    float2 f0 = __half22float2(*reinterpret_cast<__half2*>(&v.x));
    float2 f1 = __half22float2(*reinterpret_cast<__half2*>(&v.y));
    float2 f2 = __half22float2(*reinterpret_cast<__half2*>(&v.z));
    float2 f3 = __half22float2(*reinterpret_cast<__half2*>(&v.w));
    acc[0] += f0.x; acc[1] += f0.y;
    acc[2] += f1.x; acc[3] += f1.y;
    acc[4] += f2.x; acc[5] += f2.y;
    acc[6] += f3.x; acc[7] += f3.y;
}

__global__ void gather_kernel(const float* __restrict__ b,
                              float*       __restrict__ out) {
    int node = (blockIdx.x * blockDim.x + threadIdx.x) >> 5;
    int lane = threadIdx.x & 31;
    if (node >= N_NODES) return;

    int slot = lane >> 3;
    int cg   = lane & 7;

    const int* arow = &g_adj[(long)node * CAP];
    // independent loads: deg, adj row (unpredicated — always in bounds)
    int deg_raw = g_deg[node];
    int a0 = arow[lane];

    // reset for the next launch (replaces the zeroing kernel)
    if (lane == 0) g_deg[node] = 0;

    int deg = deg_raw > CAP ? CAP : deg_raw;
    int d0  = deg < 32 ? deg : 32;

    const uint4* y4 = reinterpret_cast<const uint4*>(g_yh);

    float acc[8];
#pragma unroll
    for (int i = 0; i < 8; i++) acc[i] = 0.f;

    // ---- neighbors 0..15: unconditional, 4 independent loads per lane ----
    {
        int tn[4];
        uint4 v[4];
#pragma unroll
        for (int u = 0; u < 4; u++) {
            int j = u * 4 + slot;                    // 0..15
            int id = __shfl_sync(0xFFFFFFFFu, a0, j);
            tn[u] = (j < d0) ? id : N_NODES;         // dummy zero row
        }
#pragma unroll
        for (int u = 0; u < 4; u++) v[u] = y4[(size_t)tn[u] * 8 + cg];
#pragma unroll
        for (int u = 0; u < 4; u++) acc_chunk(acc, v[u]);
    }
    // ---- neighbors 16..31: warp-uniform branch (P ~ 0.43) ----
    if (d0 > 16) {
        int tn[4];
        uint4 v[4];
#pragma unroll
        for (int u = 0; u < 4; u++) {
            int j = 16 + u * 4 + slot;               // 16..31
            int id = __shfl_sync(0xFFFFFFFFu, a0, j);
            tn[u] = (j < d0) ? id : N_NODES;
        }
#pragma unroll
        for (int u = 0; u < 4; u++) v[u] = y4[(size_t)tn[u] * 8 + cg];
#pragma unroll
        for (int u = 0; u < 4; u++) acc_chunk(acc, v[u]);
    }
    // ---- neighbors 32..63: rare tail (P(deg>32) ~ 1e-4) ----
    if (deg > 32) {
        int a1 = arow[32 + lane];
        int tn[8];
        uint4 v[8];
#pragma unroll
        for (int u = 0; u < 8; u++) {
            int j = 32 + u * 4 + slot;               // 32..63
            int id = __shfl_sync(0xFFFFFFFFu, a1, j - 32);
            tn[u] = (j < deg) ? id : N_NODES;
        }
#pragma unroll
        for (int u = 0; u < 8; u++) v[u] = y4[(size_t)tn[u] * 8 + cg];
#pragma unroll
        for (int u = 0; u < 8; u++) acc_chunk(acc, v[u]);
    }

    // reduce across the 4 slots
#pragma unroll
    for (int i = 0; i < 8; i++) acc[i] += __shfl_xor_sync(0xFFFFFFFFu, acc[i], 8);
#pragma unroll
    for (int i = 0; i < 8; i++) acc[i] += __shfl_xor_sync(0xFFFFFFFFu, acc[i], 16);

    if (slot == 0) {
        float scale = 1.0f / ((float)deg_raw + 1e-6f);
        float4 b0 = reinterpret_cast<const float4*>(b)[cg * 2];
        float4 b1 = reinterpret_cast<const float4*>(b)[cg * 2 + 1];
        float4 o0 = make_float4(acc[0] * scale + b0.x, acc[1] * scale + b0.y,
                                acc[2] * scale + b0.z, acc[3] * scale + b0.w);
        float4 o1 = make_float4(acc[4] * scale + b1.x, acc[5] * scale + b1.y,
                                acc[6] * scale + b1.z, acc[7] * scale + b1.w);
        float4* dst = reinterpret_cast<float4*>(&out[(size_t)node * D + cg * 8]);
        dst[0] = o0;
        dst[1] = o1;
    }
}

// ---------------------------------------------------------------------------
// Launch
// ---------------------------------------------------------------------------
extern "C" void kernel_launch(void* const* d_in, const int* in_sizes, int n_in,
                              void* d_out, int out_size) {
    const float* x  = (const float*)d_in[0];   // [N, 64]
    const int*   ei = (const int*)  d_in[1];   // [2, E]
    const float* W  = (const float*)d_in[2];   // [64, 64]
    const float* b  = (const float*)d_in[3];   // [64]
    float* out = (float*)d_out;                // [N, 64]

    (void)in_sizes; (void)n_in; (void)out_size;

    gemm_kernel<<<GEMM_BLOCKS, 256>>>(x, W);
    fill_kernel<<<FILL_BLOCKS, 256>>>(ei);

    // one warp per node, 8 warps per block
    gather_kernel<<<(N_NODES + 7) / 8, 256>>>(b, out);
}

// round 17
// speedup vs baseline: 1.2631x; 1.0709x over previous
#include <cuda_runtime.h>
#include <cuda_fp16.h>
#include <cuda_bf16.h>
#include <mma.h>
#include <cstdint>

// Problem constants (fixed by the reference)
#define N_NODES 100000
#define N_PAD   100096      // multiple of 128 (wmma GEMM block tile)
#define N_EDGES 1600000
#define D       64
#define CAP     64          // ELL row capacity; Poisson(16) => P(deg>64) ~ 1e-20

#define GEMM_BLOCKS (N_PAD / 128)                  // 782
#define FILL_BLOCKS ((N_EDGES / 8 + 255) / 256)    // 782

// padded shared strides (conflict-free LDSM: 144B row stride rotates banks)
#define SXS 72     // halves per row for sX/sW (64 data + 8 pad)
#define STS 20     // floats per row for the stage tile (16 data + 4 pad)

using namespace nvcuda;

// ---------------------------------------------------------------------------
// Scratch (allocation-free rule: __device__ globals). Zero-initialized at
// module load. g_deg is left zeroed by the gather kernel after each launch.
// Rows >= N_NODES of g_yh are written as zeros by the GEMM (zero-padded x),
// so the gather's dummy row N_NODES is always 0.
// ---------------------------------------------------------------------------
__device__ int    g_deg[N_NODES];
__device__ int    g_adj[(size_t)N_NODES * CAP];    // 25.6 MB, ELL layout
__device__ __half g_yh[(size_t)N_PAD * D];         // 12.8 MB, y = x @ W (fp16)

// ---------------------------------------------------------------------------
// Kernel 1 (fused): blocks [0, GEMM_BLOCKS): padded-smem wmma GEMM y = x @ W;
// blocks [GEMM_BLOCKS, +FILL_BLOCKS): ELL fill. GEMM-first ordering (the only
// fused ordering that measured competitive; fill tail overlaps the GEMM).
// ---------------------------------------------------------------------------
__global__ void gemm_fill_kernel(const float* __restrict__ x,
                                 const float* __restrict__ W,
                                 const int*   __restrict__ ei) {
    int t = threadIdx.x;   // 0..255

    if (blockIdx.x >= GEMM_BLOCKS) {
        // ---------------- ELL fill: 8 edges per thread ----------------
        int i = (blockIdx.x - GEMM_BLOCKS) * 256 + t;
        int e = i * 8;
        if (e >= N_EDGES) return;   // N_EDGES % 8 == 0

        int4 sa = *reinterpret_cast<const int4*>(&ei[e]);
        int4 sb = *reinterpret_cast<const int4*>(&ei[e + 4]);
        int4 ta = *reinterpret_cast<const int4*>(&ei[N_EDGES + e]);
        int4 tb = *reinterpret_cast<const int4*>(&ei[N_EDGES + e + 4]);

        int s[8]  = { sa.x, sa.y, sa.z, sa.w, sb.x, sb.y, sb.z, sb.w };
        int tt[8] = { ta.x, ta.y, ta.z, ta.w, tb.x, tb.y, tb.z, tb.w };

        int p[8];
#pragma unroll
        for (int u = 0; u < 8; u++) p[u] = atomicAdd(&g_deg[s[u]], 1);
#pragma unroll
        for (int u = 0; u < 8; u++)
            if (p[u] < CAP) g_adj[(long)s[u] * CAP + p[u]] = tt[u];
        return;
    }

    // ------------- padded wmma GEMM: 128 rows/block, 16/warp --------------
    __shared__ alignas(16) __half sW[D * SXS];          //  9.2 KB
    __shared__ alignas(16) __half sX[128 * SXS];        // 18.4 KB
    __shared__ alignas(16) float  stage[8 * 16 * STS];  // 10.2 KB

    int rows0 = blockIdx.x * 128;
    int w     = t >> 5;        // warp 0..7
    int lane  = t & 31;

    // Convert W -> fp16 smem (1024 float4, 4 per thread), padded rows
    {
        const float4* W4 = reinterpret_cast<const float4*>(W);
#pragma unroll
        for (int i = 0; i < 4; i++) {
            int f  = t + i * 256;          // float4 index (packed)
            int k  = f >> 4;               // row 0..63
            int jg = f & 15;               // float4-group within row
            float4 v = W4[f];
            __half2 h0 = __floats2half2_rn(v.x, v.y);
            __half2 h1 = __floats2half2_rn(v.z, v.w);
            *reinterpret_cast<uint2*>(&sW[k * SXS + jg * 4]) =
                make_uint2(*reinterpret_cast<unsigned int*>(&h0),
                           *reinterpret_cast<unsigned int*>(&h1));
        }
    }
    // Convert x tile -> fp16 smem (2048 float4, 8 per thread); pad rows = 0
    {
        const float4* X4 = reinterpret_cast<const float4*>(x);
#pragma unroll
        for (int i = 0; i < 8; i++) {
            int f   = t + i * 256;         // float4 index within packed tile
            int row = f >> 4;              // tile row 0..127
            int jg  = f & 15;
            int gn  = rows0 + row;
            float4 v = make_float4(0.f, 0.f, 0.f, 0.f);
            if (gn < N_NODES)
                v = X4[(size_t)gn * (D / 4) + jg];
            __half2 h0 = __floats2half2_rn(v.x, v.y);
            __half2 h1 = __floats2half2_rn(v.z, v.w);
            *reinterpret_cast<uint2*>(&sX[row * SXS + jg * 4]) =
                make_uint2(*reinterpret_cast<unsigned int*>(&h0),
                           *reinterpret_cast<unsigned int*>(&h1));
        }
    }
    __syncthreads();

    // A fragments for this warp's 16 rows (k = 0..3)
    wmma::fragment<wmma::matrix_a, 16, 16, 16, __half, wmma::row_major> af[4];
#pragma unroll
    for (int k = 0; k < 4; k++)
        wmma::load_matrix_sync(af[k], sX + (w * 16) * SXS + k * 16, SXS);

    float* st = stage + w * 16 * STS;

#pragma unroll
    for (int n = 0; n < 4; n++) {
        wmma::fragment<wmma::accumulator, 16, 16, 16, float> cf;
        wmma::fill_fragment(cf, 0.0f);
#pragma unroll
        for (int k = 0; k < 4; k++) {
            wmma::fragment<wmma::matrix_b, 16, 16, 16, __half, wmma::row_major> bf;
            wmma::load_matrix_sync(bf, sW + (k * 16) * SXS + n * 16, SXS);
            wmma::mma_sync(cf, af[k], bf, cf);
        }
        wmma::store_matrix_sync(st, cf, STS, wmma::mem_row_major);
        __syncwarp();

        // convert + store this 16x16 tile: lane -> (row = lane>>1, 8 cols)
        int r  = lane >> 1;
        int c0 = (lane & 1) * 8;
        int grow = rows0 + w * 16 + r;
        const float* sp = st + r * STS + c0;
        __half2 h0 = __floats2half2_rn(sp[0], sp[1]);
        __half2 h1 = __floats2half2_rn(sp[2], sp[3]);
        __half2 h2 = __floats2half2_rn(sp[4], sp[5]);
        __half2 h3 = __floats2half2_rn(sp[6], sp[7]);
        uint4 pk = make_uint4(*reinterpret_cast<unsigned int*>(&h0),
                              *reinterpret_cast<unsigned int*>(&h1),
                              *reinterpret_cast<unsigned int*>(&h2),
                              *reinterpret_cast<unsigned int*>(&h3));
        reinterpret_cast<uint4*>(g_yh)[((size_t)grow * D + n * 16 + c0) / 8] = pk;
        __syncwarp();
    }
}

// ---------------------------------------------------------------------------
// Kernel 2: gather over y + normalize + bias -> out (final)
// EXACT R9 structure (measured 36-37.5 us six times). One warp per node.
// Lane = (slot, colgrp): slot=lane>>3, cg=lane&7.
// Degree-adaptive: neighbors 0..15 unconditional, 16..31 warp-uniform branch,
// 32..63 rare tail. Resets g_deg[node]=0 for the next launch.
// ---------------------------------------------------------------------------
__device__ __forceinline__ void acc_chunk(float acc[8], uint4 v) {
    float2 f0 = __half22float2(*reinterpret_cast<__half2*>(&v.x));
    float2 f1 = __half22float2(*reinterpret_cast<__half2*>(&v.y));
    float2 f2 = __half22float2(*reinterpret_cast<__half2*>(&v.z));
    float2 f3 = __half22float2(*reinterpret_cast<__half2*>(&v.w));
    acc[0] += f0.x; acc[1] += f0.y;
    acc[2] += f1.x; acc[3] += f1.y;
    acc[4] += f2.x; acc[5] += f2.y;
    acc[6] += f3.x; acc[7] += f3.y;
}

__global__ void gather_kernel(const float* __restrict__ b,
                              float*       __restrict__ out) {
    int node = (blockIdx.x * blockDim.x + threadIdx.x) >> 5;
    int lane = threadIdx.x & 31;
    if (node >= N_NODES) return;

    int slot = lane >> 3;
    int cg   = lane & 7;

    const int* arow = &g_adj[(long)node * CAP];
    // independent loads: deg, adj row (unpredicated — always in bounds)
    int deg_raw = g_deg[node];
    int a0 = arow[lane];

    // reset for the next launch (replaces the zeroing kernel)
    if (lane == 0) g_deg[node] = 0;

    int deg = deg_raw > CAP ? CAP : deg_raw;
    int d0  = deg < 32 ? deg : 32;

    const uint4* y4 = reinterpret_cast<const uint4*>(g_yh);

    float acc[8];
#pragma unroll
    for (int i = 0; i < 8; i++) acc[i] = 0.f;

    // ---- neighbors 0..15: unconditional, 4 independent loads per lane ----
    {
        int tn[4];
        uint4 v[4];
#pragma unroll
        for (int u = 0; u < 4; u++) {
            int j = u * 4 + slot;                    // 0..15
            int id = __shfl_sync(0xFFFFFFFFu, a0, j);
            tn[u] = (j < d0) ? id : N_NODES;         // dummy zero row
        }
#pragma unroll
        for (int u = 0; u < 4; u++) v[u] = y4[(size_t)tn[u] * 8 + cg];
#pragma unroll
        for (int u = 0; u < 4; u++) acc_chunk(acc, v[u]);
    }
    // ---- neighbors 16..31: warp-uniform branch (P ~ 0.43) ----
    if (d0 > 16) {
        int tn[4];
        uint4 v[4];
#pragma unroll
        for (int u = 0; u < 4; u++) {
            int j = 16 + u * 4 + slot;               // 16..31
            int id = __shfl_sync(0xFFFFFFFFu, a0, j);
            tn[u] = (j < d0) ? id : N_NODES;
        }
#pragma unroll
        for (int u = 0; u < 4; u++) v[u] = y4[(size_t)tn[u] * 8 + cg];
#pragma unroll
        for (int u = 0; u < 4; u++) acc_chunk(acc, v[u]);
    }
    // ---- neighbors 32..63: rare tail (P(deg>32) ~ 1e-4) ----
    if (deg > 32) {
        int a1 = arow[32 + lane];
        int tn[8];
        uint4 v[8];
#pragma unroll
        for (int u = 0; u < 8; u++) {
            int j = 32 + u * 4 + slot;               // 32..63
            int id = __shfl_sync(0xFFFFFFFFu, a1, j - 32);
            tn[u] = (j < deg) ? id : N_NODES;
        }
#pragma unroll
        for (int u = 0; u < 8; u++) v[u] = y4[(size_t)tn[u] * 8 + cg];
#pragma unroll
        for (int u = 0; u < 8; u++) acc_chunk(acc, v[u]);
    }

    // reduce across the 4 slots
#pragma unroll
    for (int i = 0; i < 8; i++) acc[i] += __shfl_xor_sync(0xFFFFFFFFu, acc[i], 8);
#pragma unroll
    for (int i = 0; i < 8; i++) acc[i] += __shfl_xor_sync(0xFFFFFFFFu, acc[i], 16);

    if (slot == 0) {
        float scale = 1.0f / ((float)deg_raw + 1e-6f);
        float4 b0 = reinterpret_cast<const float4*>(b)[cg * 2];
        float4 b1 = reinterpret_cast<const float4*>(b)[cg * 2 + 1];
        float4 o0 = make_float4(acc[0] * scale + b0.x, acc[1] * scale + b0.y,
                                acc[2] * scale + b0.z, acc[3] * scale + b0.w);
        float4 o1 = make_float4(acc[4] * scale + b1.x, acc[5] * scale + b1.y,
                                acc[6] * scale + b1.z, acc[7] * scale + b1.w);
        float4* dst = reinterpret_cast<float4*>(&out[(size_t)node * D + cg * 8]);
        dst[0] = o0;
        dst[1] = o1;
    }
}

// ---------------------------------------------------------------------------
// Launch
// ---------------------------------------------------------------------------
extern "C" void kernel_launch(void* const* d_in, const int* in_sizes, int n_in,
                              void* d_out, int out_size) {
    const float* x  = (const float*)d_in[0];   // [N, 64]
    const int*   ei = (const int*)  d_in[1];   // [2, E]
    const float* W  = (const float*)d_in[2];   // [64, 64]
    const float* b  = (const float*)d_in[3];   // [64]
    float* out = (float*)d_out;                // [N, 64]

    (void)in_sizes; (void)n_in; (void)out_size;

    gemm_fill_kernel<<<GEMM_BLOCKS + FILL_BLOCKS, 256>>>(x, W, ei);

    // one warp per node, 8 warps per block
    gather_kernel<<<(N_NODES + 7) / 8, 256>>>(b, out);
}